// round 8
// baseline (speedup 1.0000x reference)
#include <cuda_runtime.h>
#include <cuda_bf16.h>
#include <cstdint>

// x:   [B=64, C=12, 224, 224] fp32
// w:   [C=12, E=768] fp32
// out: [B=64, P=196, E=768] fp32
//
// CTA = 2x2 patch block (32x32 pixels x 12 channels = 48 KB of x).
// Phase 1: warp = channel, 8 full-line float4 loads per thread in two
//          batches of 4 (caps register staging at ~4 float4 so we fit
//          4 CTAs/SM), dual shuffle-reduce -> pooled[12][4].
// Phase 2: each thread loads w[:, e4] once and emits TWO patch outputs.

#define IMG    224
#define NP     14
#define C_IN   12
#define EMBED  768
#define NTH    384

__device__ __forceinline__ float4 ldcs4(const float* p) {
    return __ldcs(reinterpret_cast<const float4*>(p));
}

__global__ __launch_bounds__(NTH, 4) void patch_block_kernel(
    const float* __restrict__ x,
    const float* __restrict__ w,
    float* __restrict__ out)
{
    const int pp  = blockIdx.x;        // patch-col pair 0..6
    const int pr  = blockIdx.y;        // patch-row pair 0..6
    const int b   = blockIdx.z;        // 0..63
    const int t   = threadIdx.x;
    const int warp = t >> 5;           // channel 0..11
    const int lane = t & 31;
    const int q8  = lane & 7;          // float4 col within the 32-float row
    const int rh  = lane >> 3;         // row phase 0..3

    __shared__ float pooled[C_IN][4];  // [channel][prow*2 + pcol]

    // ---- Phase 1: pool a 32x32 region of channel `warp` ----
    const float* base = x
        + (((size_t)(b * C_IN + warp)) * IMG + (size_t)pr * 32 + rh) * IMG
        + (size_t)pp * 32 + q8 * 4;

    // Batch A: top patch-row (rows rh + {0,4,8,12})
    float4 u0 = ldcs4(base + (size_t)(4 * 0) * IMG);
    float4 u1 = ldcs4(base + (size_t)(4 * 1) * IMG);
    float4 u2 = ldcs4(base + (size_t)(4 * 2) * IMG);
    float4 u3 = ldcs4(base + (size_t)(4 * 3) * IMG);
    float st = (((u0.x + u0.y) + (u0.z + u0.w)) + ((u1.x + u1.y) + (u1.z + u1.w)))
             + (((u2.x + u2.y) + (u2.z + u2.w)) + ((u3.x + u3.y) + (u3.z + u3.w)));

    // Batch B: bottom patch-row (rows rh + {16,20,24,28})
    float4 d0 = ldcs4(base + (size_t)(4 * 4) * IMG);
    float4 d1 = ldcs4(base + (size_t)(4 * 5) * IMG);
    float4 d2 = ldcs4(base + (size_t)(4 * 6) * IMG);
    float4 d3 = ldcs4(base + (size_t)(4 * 7) * IMG);
    float sb = (((d0.x + d0.y) + (d0.z + d0.w)) + ((d1.x + d1.y) + (d1.z + d1.w)))
             + (((d2.x + d2.y) + (d2.z + d2.w)) + ((d3.x + d3.y) + (d3.z + d3.w)));

    // Fold lane bits 0,1 (float4 cols within a patch) and 3,4 (row phases);
    // bit 2 (q8>>2) = patch column survives.
    st += __shfl_xor_sync(0xffffffffu, st, 1);
    sb += __shfl_xor_sync(0xffffffffu, sb, 1);
    st += __shfl_xor_sync(0xffffffffu, st, 2);
    sb += __shfl_xor_sync(0xffffffffu, sb, 2);
    st += __shfl_xor_sync(0xffffffffu, st, 8);
    sb += __shfl_xor_sync(0xffffffffu, sb, 8);
    st += __shfl_xor_sync(0xffffffffu, st, 16);
    sb += __shfl_xor_sync(0xffffffffu, sb, 16);

    if ((lane & 27) == 0) {            // lanes 0 and 4
        const int pc = (lane >> 2) & 1;
        pooled[warp][pc]     = st;     // top patch row
        pooled[warp][2 + pc] = sb;     // bottom patch row
    }
    __syncthreads();

    // ---- Phase 2: one w column read serves two patch outputs ----
    const int e4 = t % 192;            // output float4 slot
    const int lr = t / 192;            // local patch row 0/1 (uniform per warp)

    float4 acc0 = make_float4(0.f, 0.f, 0.f, 0.f);  // patch col 0
    float4 acc1 = make_float4(0.f, 0.f, 0.f, 0.f);  // patch col 1
    #pragma unroll
    for (int c = 0; c < C_IN; ++c) {
        const float4 wv = *reinterpret_cast<const float4*>(&w[c * EMBED + e4 * 4]);
        const float p0 = pooled[c][lr * 2 + 0];
        const float p1 = pooled[c][lr * 2 + 1];
        acc0.x = fmaf(p0, wv.x, acc0.x);  acc1.x = fmaf(p1, wv.x, acc1.x);
        acc0.y = fmaf(p0, wv.y, acc0.y);  acc1.y = fmaf(p1, wv.y, acc1.y);
        acc0.z = fmaf(p0, wv.z, acc0.z);  acc1.z = fmaf(p1, wv.z, acc1.z);
        acc0.w = fmaf(p0, wv.w, acc0.w);  acc1.w = fmaf(p1, wv.w, acc1.w);
    }

    const int pi = pr * 2 + lr;        // global patch row
    const int pj = pp * 2;             // global patch col (even)
    float* o = out + ((size_t)b * (NP * NP) + (size_t)pi * NP + pj) * EMBED + e4 * 4;
    *reinterpret_cast<float4*>(o)         = acc0;   // patch (pi, pj)
    *reinterpret_cast<float4*>(o + EMBED) = acc1;   // patch (pi, pj+1)
}

extern "C" void kernel_launch(void* const* d_in, const int* in_sizes, int n_in,
                              void* d_out, int out_size)
{
    const float* x = (const float*)d_in[0];
    const float* w = (const float*)d_in[1];
    float* out = (float*)d_out;

    dim3 grid(7, 7, 64);   // 3136 CTAs
    patch_block_kernel<<<grid, NTH>>>(x, w, out);
}